// round 15
// baseline (speedup 1.0000x reference)
#include <cuda_runtime.h>
#include <cuda_bf16.h>
#include <cuda_fp16.h>
#include <cstdint>

#define N_NODES 100000
#define N_EDGES 1600000
#define IN_CH   256
#define HC      128        // HEADS*OUT_CH
#define NEG_SLOPE 0.2f

// ---------------- scratch (static device globals; no allocation) -------------
__device__ __align__(16) float    g_feat[(size_t)N_NODES * HC];    // 51.2 MB fp32
__device__ __align__(16) uint32_t g_feat16[(size_t)N_NODES * 64];  // 25.6 MB fp16x2
__device__ float g_esrc[N_NODES];
__device__ float g_etar[N_NODES];
__device__ float g_eself[N_NODES];
__device__ int   g_counts[N_NODES];
__device__ int   g_offsets[N_NODES];
__device__ int   g_cursor[N_NODES];
__device__ int   g_scan_state[128];
__device__ int   g_srcs[N_EDGES];
__device__ int   g_is32;

// ---------------- Kernel 0: zero counts + scan state + dtype sniff -----------
__global__ __launch_bounds__(1024) void k_zero(const long long* __restrict__ p) {
    int i = blockIdx.x * 1024 + threadIdx.x;
    if (i < N_NODES) g_counts[i] = 0;
    if (blockIdx.x == 0 && threadIdx.x < 128) g_scan_state[threadIdx.x] = 0;
    if (blockIdx.x == 0 && threadIdx.x == 0) {
        int f = 0;
        for (int j = 0; j < 64; j++) {
            long long v = p[j];
            if (v < 0 || v >= (long long)N_NODES) f = 1;
        }
        g_is32 = f;
    }
}

// ======================= tcgen05 GEMM (sm_103a builds only) ==================
#if defined(__CUDA_ARCH_FEAT_SM103_ALL)
__device__ __forceinline__ uint32_t smem_u32(const void* p) {
    uint32_t a;
    asm("{ .reg .u64 t; cvta.to.shared.u64 t, %1; cvt.u32.u64 %0, t; }" : "=r"(a) : "l"(p));
    return a;
}
__device__ __forceinline__ uint32_t elect_one() {
    uint32_t pred;
    asm volatile("{\n\t.reg .pred p;\n\telect.sync _|p, 0xFFFFFFFF;\n\tselp.b32 %0, 1, 0, p;\n\t}"
                 : "=r"(pred));
    return pred;
}
__device__ __forceinline__ uint64_t mk_desc(uint32_t addr) {
    return ((uint64_t)2 << 61) | ((uint64_t)1 << 46) | ((uint64_t)64 << 32) |
           ((uint64_t)1 << 16) | ((uint64_t)(addr >> 4) & 0x3FFF);
}
__device__ __forceinline__ void mma_f16_ss(uint32_t d_tmem, uint64_t a_desc,
                                           uint64_t b_desc, uint32_t idesc, uint32_t en) {
    asm volatile(
        "{\n\t.reg .pred p;\n\tsetp.ne.u32 p, %5, 0;\n\t"
        "tcgen05.mma.cta_group::1.kind::f16 [%0], %1, %2, %3, {%4, %4, %4, %4}, p;\n\t}"
        :: "r"(d_tmem), "l"(a_desc), "l"(b_desc), "r"(idesc), "r"(0u), "r"(en)
        : "memory");
}
__device__ __forceinline__ void mbar_wait(uint32_t mbar, uint32_t parity) {
    asm volatile(
        "{\n\t.reg .pred P1;\n\t"
        "WAIT_LOOP_%=:\n\t"
        "mbarrier.try_wait.parity.acquire.cta.shared::cta.b64 P1, [%0], %1, 0x989680;\n\t"
        "@P1 bra.uni WAIT_DONE_%=;\n\t"
        "bra.uni WAIT_LOOP_%=;\n\t"
        "WAIT_DONE_%=:\n\t}"
        :: "r"(mbar), "r"(parity) : "memory");
}
#endif

#define SWZ(x) ((x) ^ (((x) >> 3) & 0x70))
// idesc kind::f16: dtypeF32(b4) atypeBF16(b7) btypeBF16(b10) N/8<<17 M/16<<24
#define GEMM_IDESC ((1u<<4)|(1u<<7)|(1u<<10)|((HC/8)<<17)|((128/16)<<24))

#define SM_TMEMPTR 0
#define SM_MBAR    8
#define SM_W_HI    1024                    // 128 x 256 bf16 = 64KB
#define SM_W_LO    (SM_W_HI + 65536)
#define SM_A_BASE  (SM_W_LO + 65536)       // 2 buffers x (HI 16K + LO 16K)
#define SM_TOTAL   (SM_A_BASE + 2 * 32768) // 197632 B

// Block tile M=128 x N=128, K=256 in chunks of 64, double-buffered A. bf16x3.
__global__ __launch_bounds__(512, 1)
void k_gemm_tc5(const float* __restrict__ x, const float* __restrict__ W,
                const float* __restrict__ b, const float* __restrict__ att) {
#if defined(__CUDA_ARCH_FEAT_SM103_ALL)
    extern __shared__ char smem[];
    const uint32_t sbase = smem_u32(smem);
    const int tid  = threadIdx.x;
    const int wid  = tid >> 5;
    const int lane = tid & 31;
    const int row0 = blockIdx.x * 128;

    if (wid == 0) {
        asm volatile("tcgen05.alloc.cta_group::1.sync.aligned.shared::cta.b32 [%0], %1;"
                     :: "r"(sbase + SM_TMEMPTR), "r"(128u) : "memory");
    }
    if (wid == 0 && lane == 0) {
        asm volatile("mbarrier.init.shared.b64 [%0], %1;"
                     :: "r"(sbase + SM_MBAR), "r"(1u) : "memory");
    }
    __syncthreads();
    uint32_t tmem;
    asm volatile("ld.shared.b32 %0, [%1];" : "=r"(tmem) : "r"(sbase + SM_TMEMPTR));

    // W (128n x 256k) -> SW128 blocked atoms, hi/lo bf16 planes (once per CTA).
    for (int g = tid; g < 4096; g += 512) {
        int row = g >> 5;
        int k   = (g & 31) * 8;
        float4 v0 = *reinterpret_cast<const float4*>(&W[(size_t)row * IN_CH + k]);
        float4 v1 = *reinterpret_cast<const float4*>(&W[(size_t)row * IN_CH + k + 4]);
        float f[8] = {v0.x, v0.y, v0.z, v0.w, v1.x, v1.y, v1.z, v1.w};
        __nv_bfloat16 hb[8], lb[8];
#pragma unroll
        for (int i = 0; i < 8; i++) {
            hb[i] = __float2bfloat16_rn(f[i]);
            lb[i] = __float2bfloat16_rn(f[i] - __bfloat162float(hb[i]));
        }
        uint32_t atom = (row >> 3) + (k >> 6) * 16;
        uint32_t byte = atom * 1024 + (row & 7) * 128 + (k & 63) * 2;
        uint32_t sw = SWZ(byte);
        *reinterpret_cast<uint4*>(smem + SM_W_HI + sw) = *reinterpret_cast<uint4*>(hb);
        *reinterpret_cast<uint4*>(smem + SM_W_LO + sw) = *reinterpret_cast<uint4*>(lb);
    }

    const uint64_t w_hi_d = mk_desc(sbase + SM_W_HI);
    const uint64_t w_lo_d = mk_desc(sbase + SM_W_LO);

    int nwaits = 0;

#pragma unroll 1
    for (int c = 0; c < 4; c++) {
        int buf = c & 1;
        uint32_t a_hi_off = SM_A_BASE + buf * 32768;
        uint32_t a_lo_off = a_hi_off + 16384;

        if (c >= 2) {              // free this buffer: chunk c-2's MMAs must be done
            mbar_wait(sbase + SM_MBAR, nwaits & 1);
            nwaits++;
        }

        // A chunk: 128 rows x 64 k -> hi/lo planes (16 atoms); 2 iters/thread
        for (int g = tid; g < 1024; g += 512) {
            int row = g >> 3;
            int k   = (g & 7) * 8;
            int grow = row0 + row;
            float f[8] = {0.f, 0.f, 0.f, 0.f, 0.f, 0.f, 0.f, 0.f};
            if (grow < N_NODES) {
                float4 v0 = *reinterpret_cast<const float4*>(&x[(size_t)grow * IN_CH + c * 64 + k]);
                float4 v1 = *reinterpret_cast<const float4*>(&x[(size_t)grow * IN_CH + c * 64 + k + 4]);
                f[0]=v0.x; f[1]=v0.y; f[2]=v0.z; f[3]=v0.w;
                f[4]=v1.x; f[5]=v1.y; f[6]=v1.z; f[7]=v1.w;
            }
            __nv_bfloat16 hb[8], lb[8];
#pragma unroll
            for (int i = 0; i < 8; i++) {
                hb[i] = __float2bfloat16_rn(f[i]);
                lb[i] = __float2bfloat16_rn(f[i] - __bfloat162float(hb[i]));
            }
            uint32_t byte = (row >> 3) * 1024 + (row & 7) * 128 + k * 2;
            uint32_t sw = SWZ(byte);
            *reinterpret_cast<uint4*>(smem + a_hi_off + sw) = *reinterpret_cast<uint4*>(hb);
            *reinterpret_cast<uint4*>(smem + a_lo_off + sw) = *reinterpret_cast<uint4*>(lb);
        }
        asm volatile("fence.proxy.async.shared::cta;" ::: "memory");
        __syncthreads();

        if (wid == 0 && elect_one()) {
            uint64_t a_hi_d = mk_desc(sbase + a_hi_off);
            uint64_t a_lo_d = mk_desc(sbase + a_lo_off);
            uint64_t wbase_hi = w_hi_d + (uint64_t)c * 1024;   // 16 atoms/chunk
            uint64_t wbase_lo = w_lo_d + (uint64_t)c * 1024;
#pragma unroll
            for (int ks = 0; ks < 4; ks++) {                    // K=16 per mma
                uint64_t ah = a_hi_d + ks * 2;
                uint64_t al = a_lo_d + ks * 2;
                uint64_t bh = wbase_hi + ks * 2;
                uint64_t bl = wbase_lo + ks * 2;
                uint32_t en0 = (c == 0 && ks == 0) ? 0u : 1u;
                mma_f16_ss(tmem, ah, bh, GEMM_IDESC, en0);
                mma_f16_ss(tmem, al, bh, GEMM_IDESC, 1u);
                mma_f16_ss(tmem, ah, bl, GEMM_IDESC, 1u);
            }
            asm volatile(
                "tcgen05.commit.cta_group::1.mbarrier::arrive::one.shared::cluster.b64 [%0];"
                :: "r"(sbase + SM_MBAR) : "memory");
        }
        __syncthreads();
    }

    // drain remaining commits (chunks 2 and 3)
    mbar_wait(sbase + SM_MBAR, nwaits & 1); nwaits++;
    mbar_wait(sbase + SM_MBAR, nwaits & 1); nwaits++;
    asm volatile("tcgen05.fence::after_thread_sync;" ::: "memory");

    // epilogue: 16 warps. Row group = wid&3, column quarter = wid>>2.
    int rg   = wid & 3;
    int q    = wid >> 2;          // 0..3
    int r    = rg * 32 + lane;
    int grow = row0 + r;
    int c0   = q * 32;
    float s0 = 0.f, s1 = 0.f;
    {
        uint32_t d[32];
        asm volatile(
            "tcgen05.ld.sync.aligned.32x32b.x32.b32 "
            "{%0,%1,%2,%3,%4,%5,%6,%7,%8,%9,%10,%11,%12,%13,%14,%15,"
            "%16,%17,%18,%19,%20,%21,%22,%23,%24,%25,%26,%27,%28,%29,%30,%31}, [%32];"
            : "=r"(d[0]),"=r"(d[1]),"=r"(d[2]),"=r"(d[3]),"=r"(d[4]),"=r"(d[5]),"=r"(d[6]),"=r"(d[7]),
              "=r"(d[8]),"=r"(d[9]),"=r"(d[10]),"=r"(d[11]),"=r"(d[12]),"=r"(d[13]),"=r"(d[14]),"=r"(d[15]),
              "=r"(d[16]),"=r"(d[17]),"=r"(d[18]),"=r"(d[19]),"=r"(d[20]),"=r"(d[21]),"=r"(d[22]),"=r"(d[23]),
              "=r"(d[24]),"=r"(d[25]),"=r"(d[26]),"=r"(d[27]),"=r"(d[28]),"=r"(d[29]),"=r"(d[30]),"=r"(d[31])
            : "r"(tmem + c0));
        asm volatile("tcgen05.wait::ld.sync.aligned;" ::: "memory");
        if (grow < N_NODES) {
#pragma unroll
            for (int qq = 0; qq < 32; qq += 4) {
                float4 bv = *reinterpret_cast<const float4*>(&b[c0 + qq]);
                float4 o;
                o.x = __uint_as_float(d[qq + 0]) + bv.x;
                o.y = __uint_as_float(d[qq + 1]) + bv.y;
                o.z = __uint_as_float(d[qq + 2]) + bv.z;
                o.w = __uint_as_float(d[qq + 3]) + bv.w;
                *reinterpret_cast<float4*>(&g_feat[(size_t)grow * HC + c0 + qq]) = o;
                __half2 h0 = __floats2half2_rn(o.x, o.y);
                __half2 h1 = __floats2half2_rn(o.z, o.w);
                uint2 hv;
                hv.x = *reinterpret_cast<uint32_t*>(&h0);
                hv.y = *reinterpret_cast<uint32_t*>(&h1);
                *reinterpret_cast<uint2*>(&g_feat16[(size_t)grow * 64 + (c0 + qq) / 2]) = hv;
                const float* ov = reinterpret_cast<const float*>(&o);
#pragma unroll
                for (int i = 0; i < 4; i++) {
                    int col = c0 + qq + i;
                    s0 = fmaf(ov[i], att[2 * col],     s0);
                    s1 = fmaf(ov[i], att[2 * col + 1], s1);
                }
            }
        }
    }

    // reduce att-dot partials across the 4 quarter-warps per row (A bufs free)
    float* sh = reinterpret_cast<float*>(smem + SM_A_BASE);
    __syncthreads();
    if (q > 0) {
        sh[((q - 1) * 128 + r) * 2 + 0] = s0;
        sh[((q - 1) * 128 + r) * 2 + 1] = s1;
    }
    __syncthreads();
    if (q == 0 && grow < N_NODES) {
        float t0 = s0, t1 = s1;
#pragma unroll
        for (int u = 0; u < 3; u++) {
            t0 += sh[(u * 128 + r) * 2 + 0];
            t1 += sh[(u * 128 + r) * 2 + 1];
        }
        g_esrc[grow] = t0;
        g_etar[grow] = t1;
        float z = t0 + t1;
        float lz = z > 0.f ? z : NEG_SLOPE * z;
        g_eself[grow] = expf(lz);
    }

    __syncthreads();
    if (wid == 0 && lane == 0) {
        asm volatile("mbarrier.inval.shared.b64 [%0];" :: "r"(sbase + SM_MBAR) : "memory");
    }
    __syncthreads();
    if (wid == 0) {
        asm volatile("tcgen05.relinquish_alloc_permit.cta_group::1.sync.aligned;");
        asm volatile("tcgen05.dealloc.cta_group::1.sync.aligned.b32 %0, %1;"
                     :: "r"(tmem), "r"(128u));
    }
#else
    (void)x; (void)W; (void)b; (void)att;
#endif
}

// ---- fallback fp32 SGEMM with fused e_pre (non-sm_103a SASS only) -----------
__global__ __launch_bounds__(256) void k_gemm_fp32(const float* __restrict__ x,
                                                   const float* __restrict__ W,
                                                   const float* __restrict__ b,
                                                   const float* __restrict__ att) {
#if !defined(__CUDA_ARCH_FEAT_SM103_ALL)
    __shared__ float xs[32][132];
    __shared__ float ws[32][132];

    const int tid = threadIdx.x;
    const int tx = tid & 15;
    const int ty = tid >> 4;
    const int row0 = blockIdx.x * 128;

    float acc[8][8];
#pragma unroll
    for (int i = 0; i < 8; i++)
#pragma unroll
        for (int j = 0; j < 8; j++) acc[i][j] = 0.f;

    for (int k0 = 0; k0 < IN_CH; k0 += 32) {
#pragma unroll
        for (int l = 0; l < 4; l++) {
            int idx = tid + l * 256;
            int r  = idx >> 3;
            int kq = idx & 7;
            int grow = row0 + r;
            float4 v = make_float4(0.f, 0.f, 0.f, 0.f);
            if (grow < N_NODES)
                v = *reinterpret_cast<const float4*>(&x[(size_t)grow * IN_CH + k0 + kq * 4]);
            xs[kq * 4 + 0][r] = v.x;
            xs[kq * 4 + 1][r] = v.y;
            xs[kq * 4 + 2][r] = v.z;
            xs[kq * 4 + 3][r] = v.w;
        }
#pragma unroll
        for (int l = 0; l < 4; l++) {
            int idx = tid + l * 256;
            int cc = idx >> 3;
            int kq = idx & 7;
            float4 v = *reinterpret_cast<const float4*>(&W[(size_t)cc * IN_CH + k0 + kq * 4]);
            ws[kq * 4 + 0][cc] = v.x;
            ws[kq * 4 + 1][cc] = v.y;
            ws[kq * 4 + 2][cc] = v.z;
            ws[kq * 4 + 3][cc] = v.w;
        }
        __syncthreads();

#pragma unroll
        for (int kk = 0; kk < 32; kk++) {
            float a[8], bb[8];
            float4 a0 = *reinterpret_cast<const float4*>(&xs[kk][ty * 8]);
            float4 a1 = *reinterpret_cast<const float4*>(&xs[kk][ty * 8 + 4]);
            float4 b0 = *reinterpret_cast<const float4*>(&ws[kk][tx * 8]);
            float4 b1 = *reinterpret_cast<const float4*>(&ws[kk][tx * 8 + 4]);
            a[0]=a0.x; a[1]=a0.y; a[2]=a0.z; a[3]=a0.w;
            a[4]=a1.x; a[5]=a1.y; a[6]=a1.z; a[7]=a1.w;
            bb[0]=b0.x; bb[1]=b0.y; bb[2]=b0.z; bb[3]=b0.w;
            bb[4]=b1.x; bb[5]=b1.y; bb[6]=b1.z; bb[7]=b1.w;
#pragma unroll
            for (int i = 0; i < 8; i++)
#pragma unroll
                for (int j = 0; j < 8; j++)
                    acc[i][j] = fmaf(a[i], bb[j], acc[i][j]);
        }
        __syncthreads();
    }

#pragma unroll
    for (int i = 0; i < 8; i++) {
        int grow = row0 + ty * 8 + i;
        if (grow >= N_NODES) break;
#pragma unroll
        for (int j = 0; j < 8; j += 4) {
            int col = tx * 8 + j;
            float4 bv = *reinterpret_cast<const float4*>(&b[col]);
            float4 o;
            o.x = acc[i][j + 0] + bv.x;
            o.y = acc[i][j + 1] + bv.y;
            o.z = acc[i][j + 2] + bv.z;
            o.w = acc[i][j + 3] + bv.w;
            *reinterpret_cast<float4*>(&g_feat[(size_t)grow * HC + col]) = o;
            __half2 h0 = __floats2half2_rn(o.x, o.y);
            __half2 h1 = __floats2half2_rn(o.z, o.w);
            uint2 hv;
            hv.x = *reinterpret_cast<uint32_t*>(&h0);
            hv.y = *reinterpret_cast<uint32_t*>(&h1);
            *reinterpret_cast<uint2*>(&g_feat16[(size_t)grow * 64 + col / 2]) = hv;
        }
    }

    // fused e_pre: per-thread partial att-dots, reduce over the 16 tx threads
    __syncthreads();
    float* pbuf = &xs[0][0];
#pragma unroll
    for (int i = 0; i < 8; i++) {
        int row = ty * 8 + i;
        float s0 = 0.f, s1 = 0.f;
#pragma unroll
        for (int j = 0; j < 8; j++) {
            int col = tx * 8 + j;
            float v = acc[i][j] + b[col];
            s0 = fmaf(v, att[2 * col],     s0);
            s1 = fmaf(v, att[2 * col + 1], s1);
        }
        pbuf[(row * 16 + tx) * 2 + 0] = s0;
        pbuf[(row * 16 + tx) * 2 + 1] = s1;
    }
    __syncthreads();
    if (tid < 128) {
        int grow = row0 + tid;
        if (grow < N_NODES) {
            float t0 = 0.f, t1 = 0.f;
#pragma unroll
            for (int u = 0; u < 16; u++) {
                t0 += pbuf[(tid * 16 + u) * 2 + 0];
                t1 += pbuf[(tid * 16 + u) * 2 + 1];
            }
            g_esrc[grow] = t0;
            g_etar[grow] = t1;
            float z = t0 + t1;
            float lz = z > 0.f ? z : NEG_SLOPE * z;
            g_eself[grow] = expf(lz);
        }
    }
#else
    (void)x; (void)W; (void)b; (void)att;
#endif
}

// ---------------- Kernel 3: histogram (targets only, 4 edges/thread) ---------
__global__ __launch_bounds__(256) void k_hist(const void* __restrict__ ei) {
    int base = (blockIdx.x * blockDim.x + threadIdx.x) * 4;
    if (base >= N_EDGES) return;
    int t[4];
    if (g_is32) {
        int4 v = *reinterpret_cast<const int4*>((const int*)ei + base);
        t[0] = v.x; t[1] = v.y; t[2] = v.z; t[3] = v.w;
    } else {
        const long long* p = (const long long*)ei;
        longlong2 v0 = *reinterpret_cast<const longlong2*>(p + base);
        longlong2 v1 = *reinterpret_cast<const longlong2*>(p + base + 2);
        t[0] = (int)v0.x; t[1] = (int)v0.y; t[2] = (int)v1.x; t[3] = (int)v1.y;
    }
#pragma unroll
    for (int u = 0; u < 4; u++)
        if ((unsigned)t[u] < N_NODES) atomicAdd(&g_counts[t[u]], 1);
}

// ------- Kernel 4: fused exclusive scan, decoupled lookback (1 launch) -------
// 98 blocks = single wave; spin-lookback is deadlock-free.
#define FLAG_PARTIAL   (1 << 28)
#define FLAG_INCLUSIVE (2 << 28)
#define VAL_MASK       0x0FFFFFFF
__global__ __launch_bounds__(1024) void k_scanall() {
    __shared__ int wsum[32];
    __shared__ int s_running;
    int bid = blockIdx.x;
    int i = bid * 1024 + threadIdx.x;
    int lane = threadIdx.x & 31, wd = threadIdx.x >> 5;
    int v = (i < N_NODES) ? g_counts[i] : 0;
    int xv = v;
#pragma unroll
    for (int o = 1; o < 32; o <<= 1) {
        int y = __shfl_up_sync(0xffffffffu, xv, o);
        if (lane >= o) xv += y;
    }
    if (lane == 31) wsum[wd] = xv;
    __syncthreads();
    if (wd == 0) {
        int s = wsum[lane];
#pragma unroll
        for (int o = 1; o < 32; o <<= 1) {
            int y = __shfl_up_sync(0xffffffffu, s, o);
            if (lane >= o) s += y;
        }
        wsum[lane] = s;
    }
    __syncthreads();

    if (threadIdx.x == 0) {
        int total = wsum[31];
        if (bid == 0) {
            atomicExch(&g_scan_state[0], total | FLAG_INCLUSIVE);
            s_running = 0;
        } else {
            atomicExch(&g_scan_state[bid], total | FLAG_PARTIAL);
            int running = 0;
            int j = bid - 1;
            while (true) {
                int st;
                do { st = atomicAdd(&g_scan_state[j], 0); } while ((st >> 28) == 0);
                running += st & VAL_MASK;
                if (st & FLAG_INCLUSIVE) break;
                j--;
            }
            atomicExch(&g_scan_state[bid], (total + running) | FLAG_INCLUSIVE);
            s_running = running;
        }
    }
    __syncthreads();
    int base = s_running + (wd > 0 ? wsum[wd - 1] : 0);
    if (i < N_NODES) {
        int off = base + xv - v;
        g_offsets[i] = off;
        g_cursor[i]  = off;
    }
}

// ---------------- Kernel 5: scatter (4 edges/thread, PDL primary) ------------
__global__ __launch_bounds__(256) void k_scatter(const void* __restrict__ ei) {
#if __CUDA_ARCH__ >= 900
    cudaTriggerProgrammaticLaunchCompletion();
#endif
    int stride = gridDim.x * blockDim.x * 4;
    for (int base = (blockIdx.x * blockDim.x + threadIdx.x) * 4; base < N_EDGES;
         base += stride) {
        int t[4], s[4];
        if (g_is32) {
            const int* p = (const int*)ei;
            int4 tv = *reinterpret_cast<const int4*>(p + base);
            int4 sv = *reinterpret_cast<const int4*>(p + N_EDGES + base);
            t[0]=tv.x; t[1]=tv.y; t[2]=tv.z; t[3]=tv.w;
            s[0]=sv.x; s[1]=sv.y; s[2]=sv.z; s[3]=sv.w;
        } else {
            const long long* p = (const long long*)ei;
            longlong2 t0 = *reinterpret_cast<const longlong2*>(p + base);
            longlong2 t1 = *reinterpret_cast<const longlong2*>(p + base + 2);
            longlong2 s0 = *reinterpret_cast<const longlong2*>(p + N_EDGES + base);
            longlong2 s1 = *reinterpret_cast<const longlong2*>(p + N_EDGES + base + 2);
            t[0]=(int)t0.x; t[1]=(int)t0.y; t[2]=(int)t1.x; t[3]=(int)t1.y;
            s[0]=(int)s0.x; s[1]=(int)s0.y; s[2]=(int)s1.x; s[3]=(int)s1.y;
        }
#pragma unroll
        for (int u = 0; u < 4; u++) {
            if ((unsigned)t[u] >= N_NODES || (unsigned)s[u] >= N_NODES) continue;
            int pos = atomicAdd(&g_cursor[t[u]], 1);
            g_srcs[pos] = s[u];
        }
    }
}

// -------- Kernel 6: aggregation, one warp per node, fp16 gather, MLP=8 -------
__global__ __launch_bounds__(256) void k_agg(float* __restrict__ out) {
    int warp = (blockIdx.x * blockDim.x + threadIdx.x) >> 5;
    if (warp >= N_NODES) return;
    int lane = threadIdx.x & 31;

    const uint2* f16 = reinterpret_cast<const uint2*>(g_feat16);  // 32 uint2/node
    int off = g_offsets[warp];
    int cnt = g_counts[warp];
    float etar = g_etar[warp];

    float4 acc = make_float4(0.f, 0.f, 0.f, 0.f);
    float sum_e = 0.f;
    int j = 0;
#pragma unroll 1
    for (; j + 8 <= cnt; j += 8) {
        int sarr[8];
#pragma unroll
        for (int u = 0; u < 8; u++) sarr[u] = g_srcs[off + j + u];
        float earr[8];
#pragma unroll
        for (int u = 0; u < 8; u++) {
            float z = g_esrc[sarr[u]] + etar;
            float lz = z > 0.f ? z : NEG_SLOPE * z;
            earr[u] = expf(lz);
            sum_e += earr[u];
        }
#pragma unroll
        for (int u = 0; u < 8; u++) {
            uint2 h = f16[(size_t)sarr[u] * 32 + lane];
            float2 p0 = __half22float2(*reinterpret_cast<__half2*>(&h.x));
            float2 p1 = __half22float2(*reinterpret_cast<__half2*>(&h.y));
            acc.x = fmaf(earr[u], p0.x, acc.x);
            acc.y = fmaf(earr[u], p0.y, acc.y);
            acc.z = fmaf(earr[u], p1.x, acc.z);
            acc.w = fmaf(earr[u], p1.y, acc.w);
        }
    }
    for (; j < cnt; j++) {
        int s = g_srcs[off + j];
        float z = g_esrc[s] + etar;
        float lz = z > 0.f ? z : NEG_SLOPE * z;
        float e = expf(lz);
        sum_e += e;
        uint2 h = f16[(size_t)s * 32 + lane];
        float2 p0 = __half22float2(*reinterpret_cast<__half2*>(&h.x));
        float2 p1 = __half22float2(*reinterpret_cast<__half2*>(&h.y));
        acc.x = fmaf(e, p0.x, acc.x);
        acc.y = fmaf(e, p0.y, acc.y);
        acc.z = fmaf(e, p1.x, acc.z);
        acc.w = fmaf(e, p1.y, acc.w);
    }

    float es  = g_eself[warp];
    float inv = 1.0f / (sum_e + es);
    // self term in full fp32 precision
    float4 fs = reinterpret_cast<const float4*>(g_feat)[(size_t)warp * 32 + lane];
    float4 o;
    o.x = (acc.x + es * fs.x) * inv;
    o.y = (acc.y + es * fs.y) * inv;
    o.z = (acc.z + es * fs.z) * inv;
    o.w = (acc.w + es * fs.w) * inv;
    reinterpret_cast<float4*>(out)[(size_t)warp * 32 + lane] = o;
}

// ---------------- launch ------------------------------------------------------
extern "C" void kernel_launch(void* const* d_in, const int* in_sizes, int n_in,
                              void* d_out, int out_size) {
    const float* x   = nullptr;
    const void*  ei  = nullptr;
    const float* W   = nullptr;
    const float* b   = nullptr;
    const float* att = nullptr;
    for (int i = 0; i < n_in; i++) {
        switch (in_sizes[i]) {
            case 25600000: x   = (const float*)d_in[i]; break;
            case 3200000:  ei  = d_in[i];               break;
            case 32768:    W   = (const float*)d_in[i]; break;
            case 128:      b   = (const float*)d_in[i]; break;
            case 256:      att = (const float*)d_in[i]; break;
            default: break;
        }
    }
    float* out = (float*)d_out;
    (void)out_size;

    int scan_blocks = (N_NODES + 1023) / 1024;         // 98
    int gemm_blocks = (N_NODES + 127) / 128;           // 782
    int hist_blocks = (N_EDGES / 4 + 255) / 256;       // 1563

    k_zero<<<scan_blocks, 1024>>>((const long long*)ei);
    k_hist<<<hist_blocks, 256>>>(ei);
    k_scanall<<<scan_blocks, 1024>>>();
    k_scatter<<<592, 256>>>(ei);      // single wave, PDL trigger at entry

    cudaFuncSetAttribute(k_gemm_tc5, cudaFuncAttributeMaxDynamicSharedMemorySize, SM_TOTAL);
    {
        cudaLaunchConfig_t cfg = {};
        cfg.gridDim  = dim3(gemm_blocks);
        cfg.blockDim = dim3(512);
        cfg.dynamicSmemBytes = SM_TOTAL;
        cfg.stream = 0;
        cudaLaunchAttribute attrs[1];
        attrs[0].id = cudaLaunchAttributeProgrammaticStreamSerialization;
        attrs[0].val.programmaticStreamSerializationAllowed = 1;
        cfg.attrs = attrs;
        cfg.numAttrs = 1;
        cudaLaunchKernelEx(&cfg, k_gemm_tc5, x, W, b, att);
    }

    k_gemm_fp32<<<gemm_blocks, 256>>>(x, W, b, att);   // no-op on 103a

    int node_warp_blocks = (N_NODES * 32 + 255) / 256; // 12500
    k_agg<<<node_warp_blocks, 256>>>(out);
}